// round 7
// baseline (speedup 1.0000x reference)
#include <cuda_runtime.h>
#include <cuda_bf16.h>
#include <cstdint>
#include <cstddef>

// ---------------- problem constants ----------------
#define SS      4096
#define EMB     2048
#define PROJD   10304
#define PROJPAD 10368
#define INTERD  4096
#define CONVD   6144
#define NH      64
#define HP      64
#define SN      128
#define NG      8
#define CSZ     256
#define NCH     16
#define DTOFF   10240

// ---------------- scratch ----------------
__device__ float g_proj[(size_t)SS * PROJD];
__device__ float g_hconv[(size_t)SS * CONVD];
__device__ float g_dt2[SS * NH];
__device__ float g_acum[NH * SS];
__device__ float g_y[(size_t)SS * INTERD];
__device__ __nv_bfloat16 g_Apack[(size_t)SS * 3 * INTERD];
__device__ __nv_bfloat16 g_B1[(size_t)PROJPAD * 3 * EMB];
__device__ __nv_bfloat16 g_B2[(size_t)EMB * 3 * INTERD];

// ================= helpers =================
__device__ __forceinline__ uint32_t smem_u32(const void* p) {
    uint32_t a;
    asm("{ .reg .u64 t; cvta.to.shared.u64 t, %1; cvt.u32.u64 %0, t; }" : "=r"(a) : "l"(p));
    return a;
}
__device__ __forceinline__ void cp_async16(uint32_t saddr, const void* g) {
    asm volatile("cp.async.cg.shared.global [%0], [%1], 16;" :: "r"(saddr), "l"(g) : "memory");
}
#define CP_COMMIT() asm volatile("cp.async.commit_group;" ::: "memory")

__device__ __forceinline__ void ldsm_x4(uint32_t addr, uint32_t& r0, uint32_t& r1,
                                        uint32_t& r2, uint32_t& r3) {
    asm volatile("ldmatrix.sync.aligned.m8n8.x4.shared.b16 {%0,%1,%2,%3}, [%4];"
                 : "=r"(r0), "=r"(r1), "=r"(r2), "=r"(r3) : "r"(addr));
}
__device__ __forceinline__ void mma_bf16(float* d, const uint32_t* a, uint32_t b0, uint32_t b1) {
    asm volatile(
        "mma.sync.aligned.m16n8k16.row.col.f32.bf16.bf16.f32 "
        "{%0,%1,%2,%3}, {%4,%5,%6,%7}, {%8,%9}, {%0,%1,%2,%3};"
        : "+f"(d[0]), "+f"(d[1]), "+f"(d[2]), "+f"(d[3])
        : "r"(a[0]), "r"(a[1]), "r"(a[2]), "r"(a[3]), "r"(b0), "r"(b1));
}
__device__ __forceinline__ uint32_t pack_bf2(float x, float y) {
    __nv_bfloat16 a = __float2bfloat16(x);
    __nv_bfloat16 b = __float2bfloat16(y);
    return (uint32_t)__bfloat16_as_ushort(a) | ((uint32_t)__bfloat16_as_ushort(b) << 16);
}

// ================= split-pack (vectorized, row-ranged) =================
__global__ void pack_split(const float* __restrict__ src, __nv_bfloat16* __restrict__ dst,
                           int srcRows, int rowStart, int rowEnd, int K, int mode) {
    const int K8 = K >> 3;
    const size_t total = (size_t)(rowEnd - rowStart) * K8;
    for (size_t v = (size_t)blockIdx.x * 256 + threadIdx.x; v < total;
         v += (size_t)gridDim.x * 256) {
        const int r = rowStart + (int)(v / K8);
        const int k = (int)(v % K8) << 3;
        float x[8];
        if (r < srcRows) {
            const float4 f0 = *(const float4*)(src + (size_t)r * K + k);
            const float4 f1 = *(const float4*)(src + (size_t)r * K + k + 4);
            x[0] = f0.x; x[1] = f0.y; x[2] = f0.z; x[3] = f0.w;
            x[4] = f1.x; x[5] = f1.y; x[6] = f1.z; x[7] = f1.w;
        } else {
#pragma unroll
            for (int i = 0; i < 8; i++) x[i] = 0.f;
        }
        union { __nv_bfloat16 h[8]; uint4 u; } uh, ul;
#pragma unroll
        for (int i = 0; i < 8; i++) {
            uh.h[i] = __float2bfloat16(x[i]);
            ul.h[i] = __float2bfloat16(x[i] - __bfloat162float(uh.h[i]));
        }
        const size_t ro = (size_t)r * 3 * K + k;
        *(uint4*)(dst + ro) = uh.u;
        if (mode == 0) {
            *(uint4*)(dst + ro + K) = ul.u;
            *(uint4*)(dst + ro + 2 * K) = uh.u;
        } else {
            *(uint4*)(dst + ro + K) = uh.u;
            *(uint4*)(dst + ro + 2 * K) = ul.u;
        }
    }
}

// ================= HMMA GEMM: C[M,N] = A[M,K3] * B[N,K3]^T =================
#define GSTAGES 3
#define GSTAGE_BYTES 32768
#define GEMM_DYN_SMEM (GSTAGES * GSTAGE_BYTES)

__device__ __forceinline__ void gemm_load_stage(
    const __nv_bfloat16* __restrict__ A, const __nv_bfloat16* __restrict__ B,
    int K3, int m0, int n0, int tid, uint32_t sb, int stage, int kk) {
    const uint32_t abase = sb + stage * GSTAGE_BYTES;
    const uint32_t bbase = abase + 16384;
    const int k0 = kk * 64;
#pragma unroll
    for (int it = 0; it < 4; it++) {
        const int idx = it * 256 + tid;
        const int row = idx >> 3;
        const int ch = idx & 7;
        const int csw = ch ^ (row & 7);
        cp_async16(abase + row * 128 + csw * 16,
                   A + (size_t)(m0 + row) * K3 + k0 + ch * 8);
    }
#pragma unroll
    for (int it = 0; it < 4; it++) {
        const int idx = it * 256 + tid;
        const int row = idx >> 3;
        const int ch = idx & 7;
        const int csw = ch ^ (row & 7);
        cp_async16(bbase + row * 128 + csw * 16,
                   B + (size_t)(n0 + row) * K3 + k0 + ch * 8);
    }
}

__global__ __launch_bounds__(256, 2)
void tgemm(const __nv_bfloat16* __restrict__ A, const __nv_bfloat16* __restrict__ B,
           float* __restrict__ C, int K3, int Nvalid, int Nstride) {
    extern __shared__ char dynsm[];
    const uint32_t sb = smem_u32(dynsm);
    const int tid = threadIdx.x;
    const int lane = tid & 31;
    const int wid = tid >> 5;
    const int wm = wid & 3;
    const int wn = wid >> 2;

    const int gridM = gridDim.x;
    const int gridN = gridDim.y;
    const int bid = blockIdx.y * gridM + blockIdx.x;
    const int GM = 16;
    const int group = bid / (GM * gridN);
    const int rem = bid - group * (GM * gridN);
    const int m0 = (group * GM + (rem % GM)) * 128;
    const int n0 = (rem / GM) * 128;
    const int nK = K3 >> 6;

    float acc[2][8][4];
#pragma unroll
    for (int i = 0; i < 2; i++)
#pragma unroll
        for (int j = 0; j < 8; j++)
#pragma unroll
            for (int q = 0; q < 4; q++) acc[i][j][q] = 0.f;

    gemm_load_stage(A, B, K3, m0, n0, tid, sb, 0, 0); CP_COMMIT();
    gemm_load_stage(A, B, K3, m0, n0, tid, sb, 1, 1); CP_COMMIT();

    const int a_row = wm * 32 + (lane & 15);
    const int a_chg = lane >> 4;
    const int b_g = lane >> 3;
    const int b_row = wn * 64 + ((b_g >> 1) << 3) + (lane & 7);
    const int b_chg = b_g & 1;

    int buf = 0, nbuf = 2;
    for (int i = 0; i < nK; i++) {
        asm volatile("cp.async.wait_group 1;" ::: "memory");
        __syncthreads();
        if (i + 2 < nK) gemm_load_stage(A, B, K3, m0, n0, tid, sb, nbuf, i + 2);
        CP_COMMIT();

        const uint32_t abase = sb + buf * GSTAGE_BYTES;
        const uint32_t bbase = abase + 16384;
#pragma unroll
        for (int kk = 0; kk < 4; kk++) {
            uint32_t af[2][4];
#pragma unroll
            for (int mi = 0; mi < 2; mi++) {
                const int row = a_row + mi * 16;
                const int ch = kk * 2 + a_chg;
                const int csw = ch ^ (row & 7);
                ldsm_x4(abase + row * 128 + csw * 16,
                        af[mi][0], af[mi][1], af[mi][2], af[mi][3]);
            }
            uint32_t bf[4][4];
#pragma unroll
            for (int nb = 0; nb < 4; nb++) {
                const int row = b_row + nb * 16;
                const int ch = kk * 2 + b_chg;
                const int csw = ch ^ (row & 7);
                ldsm_x4(bbase + row * 128 + csw * 16,
                        bf[nb][0], bf[nb][1], bf[nb][2], bf[nb][3]);
            }
#pragma unroll
            for (int mi = 0; mi < 2; mi++)
#pragma unroll
                for (int nb = 0; nb < 4; nb++) {
                    mma_bf16(acc[mi][nb * 2 + 0], af[mi], bf[nb][0], bf[nb][1]);
                    mma_bf16(acc[mi][nb * 2 + 1], af[mi], bf[nb][2], bf[nb][3]);
                }
        }
        buf = (buf + 1 == GSTAGES) ? 0 : buf + 1;
        nbuf = (nbuf + 1 == GSTAGES) ? 0 : nbuf + 1;
    }

    const int erow = (lane >> 2);
    const int ecol = (lane & 3) << 1;
#pragma unroll
    for (int mi = 0; mi < 2; mi++) {
        const int r = m0 + wm * 32 + mi * 16 + erow;
#pragma unroll
        for (int f = 0; f < 8; f++) {
            const int c = n0 + wn * 64 + (f >> 1) * 16 + (f & 1) * 8 + ecol;
            if (c < Nvalid) {
                *(float2*)(C + (size_t)r * Nstride + c) =
                    make_float2(acc[mi][f][0], acc[mi][f][1]);
                *(float2*)(C + (size_t)(r + 8) * Nstride + c) =
                    make_float2(acc[mi][f][2], acc[mi][f][3]);
            }
        }
    }
}

// ---------------- depthwise causal conv (K=4) + bias + silu, 8 t/thread ----------------
__global__ void conv_silu_kernel(const float* __restrict__ cw, const float* __restrict__ cb) {
    const int c = blockIdx.x * 256 + threadIdx.x;
    const int tb = blockIdx.y * 8;
    const float w0 = cw[c * 4 + 0], w1 = cw[c * 4 + 1],
                w2 = cw[c * 4 + 2], w3 = cw[c * 4 + 3];
    const float bias = cb[c];
    float v[11];
#pragma unroll
    for (int k = 0; k < 11; k++) {
        const int tt = tb - 3 + k;
        v[k] = (tt >= 0) ? g_proj[(size_t)tt * PROJD + INTERD + c] : 0.f;
    }
#pragma unroll
    for (int j = 0; j < 8; j++) {
        const float a = bias + v[j] * w0 + v[j + 1] * w1 + v[j + 2] * w2 + v[j + 3] * w3;
        g_hconv[(size_t)(tb + j) * CONVD + c] = a / (1.f + __expf(-a));
    }
}

// ---------------- fused softplus(dt)+cumsum per (chunk, head) ----------------
__global__ void dtacum_kernel(const float* __restrict__ dt_bias,
                              const float* __restrict__ A_log) {
    const int chunk = blockIdx.x;
    const int h = blockIdx.y;
    const int tid = threadIdx.x;
    const float Ah = -expf(A_log[h]);
    const float bias = dt_bias[h];
    __shared__ float s[CSZ];
    const int t = chunk * CSZ + tid;
    const float x = g_proj[(size_t)t * PROJD + DTOFF + h] + bias;
    const float dt2 = (x > 20.f) ? x : log1pf(expf(x));
    g_dt2[t * NH + h] = dt2;
    s[tid] = Ah * dt2;
    for (int off = 1; off < CSZ; off <<= 1) {
        __syncthreads();
        const float v = (tid >= off) ? s[tid - off] : 0.f;
        __syncthreads();
        s[tid] += v;
    }
    g_acum[h * SS + t] = s[tid];
}

// ================= SSD via HMMA (split-bf16 3-term), 2-way i-split =================
// Each CTA handles 128 i-rows (blockIdx.z half) of one (chunk, head), all 4 j-tiles.
// smem: Chi/Clo 128x128 (32KB each); B hi/lo 64x128 (16KB each) overlapped with
// Gw hi/lo 128x64 (16KB each); X hi/lo transposed 64x64 (8KB each).
// Total exactly 114688 B -> 2 CTAs/SM. Decay exponents read from g_acum via L1.
#define S_CHI 0
#define S_CLO 32768
#define S_BHI 65536
#define S_BLO 81920
#define S_GWH 65536
#define S_GWL 81920
#define S_XHI 98304
#define S_XLO 106496
#define SSD_DYN_SMEM 114688

__global__ __launch_bounds__(256, 2)
void ssd_hmma(const float* __restrict__ Dp) {
    extern __shared__ char sm[];
    const uint32_t sb = smem_u32(sm);
    const int tid = threadIdx.x;
    const int lane = tid & 31;
    const int w = tid >> 5;
    const int chunk = blockIdx.x;
    const int h = blockIdx.y;
    const int ih = blockIdx.z;            // i-half: 0 or 1
    const int t0 = chunk * CSZ;
    const int ibase = ih * 128;           // global i offset within chunk
    const int grp = h & 7;
    const int Bbase = INTERD + grp * SN;
    const int Cbase = INTERD + NG * SN + grp * SN;
    const int i0 = w * 16;                // local i-rows [i0, i0+16) per warp

    const float* acum = g_acum + h * SS + t0;
    const float alast = acum[CSZ - 1];
    const int ro = lane >> 2;
    const int co = (lane & 3) * 2;
    // this thread's two accumulator i-rows (local within the 128-row half)
    const int r1 = i0 + ro;
    const int r2 = r1 + 8;
    const float a1 = acum[ibase + r1];
    const float a2 = acum[ibase + r2];

    // load + split C: 128 rows x 128 n (256B rows, 16 chunks, swizzled)
#pragma unroll 4
    for (int it = 0; it < 8; it++) {
        const int u = it * 256 + tid;
        const int i = u >> 4;
        const int nb = u & 15;
        const float* src = g_hconv + (size_t)(t0 + ibase + i) * CONVD + Cbase + nb * 8;
        const float4 f0 = *(const float4*)(src);
        const float4 f1 = *(const float4*)(src + 4);
        const float xv[8] = {f0.x, f0.y, f0.z, f0.w, f1.x, f1.y, f1.z, f1.w};
        union { __nv_bfloat16 b[8]; uint4 u4; } hh, ll;
#pragma unroll
        for (int q = 0; q < 8; q++) {
            hh.b[q] = __float2bfloat16(xv[q]);
            ll.b[q] = __float2bfloat16(xv[q] - __bfloat162float(hh.b[q]));
        }
        const int csw = nb ^ (i & 7);
        *(uint4*)(sm + S_CHI + i * 256 + csw * 16) = hh.u4;
        *(uint4*)(sm + S_CLO + i * 256 + csw * 16) = ll.u4;
    }

    float yacc[8][4];
#pragma unroll
    for (int nb = 0; nb < 8; nb++)
#pragma unroll
        for (int q = 0; q < 4; q++) yacc[nb][q] = 0.f;

    for (int jt = 0; jt < 4; jt++) {
        const int jb = jt * 64;
        if (jt > 0) __syncthreads();      // prior stage2 reads done before overwrite
        // load + split B tile: 64 rows x 128 n
#pragma unroll
        for (int it = 0; it < 4; it++) {
            const int u = it * 256 + tid;
            const int j = u >> 4;
            const int nb = u & 15;
            const float* src = g_hconv + (size_t)(t0 + jb + j) * CONVD + Bbase + nb * 8;
            const float4 f0 = *(const float4*)(src);
            const float4 f1 = *(const float4*)(src + 4);
            const float xv[8] = {f0.x, f0.y, f0.z, f0.w, f1.x, f1.y, f1.z, f1.w};
            union { __nv_bfloat16 b[8]; uint4 u4; } hh, ll;
#pragma unroll
            for (int q = 0; q < 8; q++) {
                hh.b[q] = __float2bfloat16(xv[q]);
                ll.b[q] = __float2bfloat16(xv[q] - __bfloat162float(hh.b[q]));
            }
            const int csw = nb ^ (j & 7);
            *(uint4*)(sm + S_BHI + j * 256 + csw * 16) = hh.u4;
            *(uint4*)(sm + S_BLO + j * 256 + csw * 16) = ll.u4;
        }
        // load + split X (hid*dt2), store TRANSPOSED [p][j] (128B rows, swizzled)
#pragma unroll
        for (int it = 0; it < 4; it++) {
            const int u = it * 256 + tid;
            const int j = u >> 4;
            const int pb = (u & 15) * 4;
            const int tj = t0 + jb + j;
            float4 v = *(const float4*)(g_hconv + (size_t)tj * CONVD + h * HP + pb);
            const float sc = g_dt2[tj * NH + h];
            const float xv[4] = {v.x * sc, v.y * sc, v.z * sc, v.w * sc};
            const int wo = (j * 2) & 15;
            const int chn = j >> 3;
#pragma unroll
            for (int q = 0; q < 4; q++) {
                const int p = pb + q;
                const __nv_bfloat16 hb = __float2bfloat16(xv[q]);
                const __nv_bfloat16 lb = __float2bfloat16(xv[q] - __bfloat162float(hb));
                const uint32_t ad = p * 128 + ((chn ^ (p & 7)) << 4) + wo;
                *(__nv_bfloat16*)(sm + S_XHI + ad) = hb;
                *(__nv_bfloat16*)(sm + S_XLO + ad) = lb;
            }
        }
        __syncthreads();

        // ---- stage 1: Gram (16 i-rows per warp x 64 j), K = 128 x 3 terms ----
        float gacc[8][4];
#pragma unroll
        for (int nb = 0; nb < 8; nb++)
#pragma unroll
            for (int q = 0; q < 4; q++) gacc[nb][q] = 0.f;

        for (int term = 0; term < 3; term++) {
            const uint32_t Ab = sb + ((term == 1) ? S_CLO : S_CHI);
            const uint32_t Bb = sb + ((term == 2) ? S_BLO : S_BHI);
#pragma unroll
            for (int ks = 0; ks < 8; ks++) {
                uint32_t af[4];
                {
                    const int row = i0 + (lane & 15);
                    const int ch = 2 * ks + (lane >> 4);
                    const int csw = ch ^ (row & 7);
                    ldsm_x4(Ab + row * 256 + csw * 16, af[0], af[1], af[2], af[3]);
                }
#pragma unroll
                for (int q = 0; q < 4; q++) {
                    const int bg = lane >> 3;
                    const int row = q * 16 + ((bg >> 1) << 3) + (lane & 7);
                    const int ch = 2 * ks + (bg & 1);
                    const int csw = ch ^ (row & 7);
                    uint32_t b0, b1, b2, b3;
                    ldsm_x4(Bb + row * 256 + csw * 16, b0, b1, b2, b3);
                    mma_bf16(gacc[q * 2 + 0], af, b0, b1);
                    mma_bf16(gacc[q * 2 + 1], af, b2, b3);
                }
            }
        }

        // ---- weight in-register (decay exponents from gmem via L1) ----
        const int gr1 = ibase + r1;       // global-within-chunk i indices
        const int gr2 = ibase + r2;
#pragma unroll
        for (int nb = 0; nb < 8; nb++) {
            const int cb = (nb >> 1) * 16 + (nb & 1) * 8 + co;
            const int jg = jb + cb;
            const float aj0 = acum[jg];
            const float aj1 = acum[jg + 1];
            float wv;
            wv = __expf(a1 - aj0 + alast) + ((jg <= gr1) ? __expf(a1 - aj0) : 0.f);
            gacc[nb][0] *= wv;
            wv = __expf(a1 - aj1 + alast) + ((jg + 1 <= gr1) ? __expf(a1 - aj1) : 0.f);
            gacc[nb][1] *= wv;
            wv = __expf(a2 - aj0 + alast) + ((jg <= gr2) ? __expf(a2 - aj0) : 0.f);
            gacc[nb][2] *= wv;
            wv = __expf(a2 - aj1 + alast) + ((jg + 1 <= gr2) ? __expf(a2 - aj1) : 0.f);
            gacc[nb][3] *= wv;
        }
        __syncthreads();   // all B reads complete before Gw overwrites the B region

        // ---- store Gw hi/lo to smem (128B rows, swizzled) ----
#pragma unroll
        for (int nb = 0; nb < 8; nb++) {
            const int c = (nb >> 1) * 16 + (nb & 1) * 8 + co;
            const int chn = c >> 3;
            const int wo = (c * 2) & 15;
            const uint32_t ad1 = r1 * 128 + ((chn ^ (r1 & 7)) << 4) + wo;
            const uint32_t ad2 = r2 * 128 + ((chn ^ (r2 & 7)) << 4) + wo;
            *(uint32_t*)(sm + S_GWH + ad1) = pack_bf2(gacc[nb][0], gacc[nb][1]);
            *(uint32_t*)(sm + S_GWL + ad1) = pack_bf2(
                gacc[nb][0] - __bfloat162float(__float2bfloat16(gacc[nb][0])),
                gacc[nb][1] - __bfloat162float(__float2bfloat16(gacc[nb][1])));
            *(uint32_t*)(sm + S_GWH + ad2) = pack_bf2(gacc[nb][2], gacc[nb][3]);
            *(uint32_t*)(sm + S_GWL + ad2) = pack_bf2(
                gacc[nb][2] - __bfloat162float(__float2bfloat16(gacc[nb][2])),
                gacc[nb][3] - __bfloat162float(__float2bfloat16(gacc[nb][3])));
        }
        __syncthreads();

        // ---- stage 2: Y += Gw @ X^T, K = 64 x 3 terms ----
        for (int term = 0; term < 3; term++) {
            const uint32_t Ab = sb + ((term == 1) ? S_GWL : S_GWH);
            const uint32_t Bb = sb + ((term == 2) ? S_XLO : S_XHI);
#pragma unroll
            for (int ks = 0; ks < 4; ks++) {
                uint32_t af[4];
                {
                    const int row = i0 + (lane & 15);
                    const int ch = 2 * ks + (lane >> 4);
                    const int csw = ch ^ (row & 7);
                    ldsm_x4(Ab + row * 128 + csw * 16, af[0], af[1], af[2], af[3]);
                }
#pragma unroll
                for (int q = 0; q < 4; q++) {
                    const int bg = lane >> 3;
                    const int row = q * 16 + ((bg >> 1) << 3) + (lane & 7);
                    const int ch = 2 * ks + (bg & 1);
                    const int csw = ch ^ (row & 7);
                    uint32_t b0, b1, b2, b3;
                    ldsm_x4(Bb + row * 128 + csw * 16, b0, b1, b2, b3);
                    mma_bf16(yacc[q * 2 + 0], af, b0, b1);
                    mma_bf16(yacc[q * 2 + 1], af, b2, b3);
                }
            }
        }
    }

    // ---- epilogue: D residual + store Y ----
    const float Dh = Dp[h];
    const int gr1 = t0 + ibase + r1;
    const int gr2 = t0 + ibase + r2;
#pragma unroll
    for (int nb = 0; nb < 8; nb++) {
        const int p = (nb >> 1) * 16 + (nb & 1) * 8 + co;
        const float2 h1 = *(const float2*)(g_hconv + (size_t)gr1 * CONVD + h * HP + p);
        const float2 h2 = *(const float2*)(g_hconv + (size_t)gr2 * CONVD + h * HP + p);
        *(float2*)(g_y + (size_t)gr1 * INTERD + h * HP + p) =
            make_float2(yacc[nb][0] + Dh * h1.x, yacc[nb][1] + Dh * h1.y);
        *(float2*)(g_y + (size_t)gr2 * INTERD + h * HP + p) =
            make_float2(yacc[nb][2] + Dh * h2.x, yacc[nb][3] + Dh * h2.y);
    }
}

// ---------------- gate silu + RMSNorm + split-bf16 A-pack (fused) ----------------
__global__ void norm_pack_kernel(const float* __restrict__ norm_w) {
    const int t = blockIdx.x;
    const int tid = threadIdx.x;
    __shared__ float red[256];
    __shared__ float yg_s[INTERD];
    float local = 0.f;
    for (int c = tid; c < INTERD; c += 256) {
        const float g = g_proj[(size_t)t * PROJD + c];
        const float yv = g_y[(size_t)t * INTERD + c];
        const float yg = yv * (g / (1.f + __expf(-g)));
        yg_s[c] = yg;
        local += yg * yg;
    }
    red[tid] = local;
    __syncthreads();
    for (int s = 128; s > 0; s >>= 1) {
        if (tid < s) red[tid] += red[tid + s];
        __syncthreads();
    }
    const float rstd = rsqrtf(red[0] / (float)INTERD + 1e-6f);
    __nv_bfloat16* dst = g_Apack + (size_t)t * 3 * INTERD;
    for (int c = tid * 4; c < INTERD; c += 1024) {
        union { __nv_bfloat16 h[4]; uint2 u; } uh, ul;
#pragma unroll
        for (int i = 0; i < 4; i++) {
            const float v = norm_w[c + i] * yg_s[c + i] * rstd;
            uh.h[i] = __float2bfloat16(v);
            ul.h[i] = __float2bfloat16(v - __bfloat162float(uh.h[i]));
        }
        *(uint2*)(dst + c) = uh.u;
        *(uint2*)(dst + INTERD + c) = ul.u;
        *(uint2*)(dst + 2 * INTERD + c) = uh.u;
    }
}

// ---------------- launch ----------------
extern "C" void kernel_launch(void* const* d_in, const int* in_sizes, int n_in,
                              void* d_out, int out_size) {
    (void)in_sizes; (void)n_in; (void)out_size;
    const float* x       = (const float*)d_in[0];
    const float* w_in    = (const float*)d_in[1];
    const float* conv_w  = (const float*)d_in[2];
    const float* conv_b  = (const float*)d_in[3];
    const float* dt_bias = (const float*)d_in[4];
    const float* A_log   = (const float*)d_in[5];
    const float* Dv      = (const float*)d_in[6];
    const float* norm_w  = (const float*)d_in[7];
    const float* w_out   = (const float*)d_in[8];
    float* out = (float*)d_out;

    float* p_proj = nullptr;
    __nv_bfloat16* p_Apack = nullptr;
    __nv_bfloat16* p_B1 = nullptr;
    __nv_bfloat16* p_B2 = nullptr;
    cudaGetSymbolAddress((void**)&p_proj, g_proj);
    cudaGetSymbolAddress((void**)&p_Apack, g_Apack);
    cudaGetSymbolAddress((void**)&p_B1, g_B1);
    cudaGetSymbolAddress((void**)&p_B2, g_B2);

    cudaFuncSetAttribute(tgemm, cudaFuncAttributeMaxDynamicSharedMemorySize, GEMM_DYN_SMEM);
    cudaFuncSetAttribute(ssd_hmma, cudaFuncAttributeMaxDynamicSharedMemorySize, SSD_DYN_SMEM);

    // --- GEMM1 packs (split so tgemm is the 4th launch for ncu) ---
    pack_split<<<2048, 256>>>(x, p_Apack, SS, 0, SS, EMB, 0);
    pack_split<<<2048, 256>>>(w_in, p_B1, PROJD, 0, PROJPAD / 2, EMB, 1);
    pack_split<<<2048, 256>>>(w_in, p_B1, PROJD, PROJPAD / 2, PROJPAD, EMB, 1);
    // --- GEMM1: proj = X @ W_in^T ---
    tgemm<<<dim3(SS / 128, PROJPAD / 128), 256, GEMM_DYN_SMEM>>>(
        p_Apack, p_B1, p_proj, 3 * EMB, PROJD, PROJD);

    // --- elementwise / scan stages ---
    conv_silu_kernel<<<dim3(CONVD / 256, SS / 8), 256>>>(conv_w, conv_b);
    dtacum_kernel<<<dim3(NCH, NH), CSZ>>>(dt_bias, A_log);
    ssd_hmma<<<dim3(NCH, NH, 2), 256, SSD_DYN_SMEM>>>(Dv);
    norm_pack_kernel<<<SS, 256>>>(norm_w);

    // --- GEMM2: out = normed @ W_out^T ---
    pack_split<<<2048, 256>>>(w_out, p_B2, EMB, 0, EMB, INTERD, 1);
    tgemm<<<dim3(SS / 128, EMB / 128), 256, GEMM_DYN_SMEM>>>(
        p_Apack, p_B2, out, 3 * INTERD, EMB, EMB);
}

// round 9
// speedup vs baseline: 1.0194x; 1.0194x over previous
#include <cuda_runtime.h>
#include <cuda_bf16.h>
#include <cstdint>
#include <cstddef>

// ---------------- problem constants ----------------
#define SS      4096
#define EMB     2048
#define PROJD   10304
#define PROJPAD 10368
#define INTERD  4096
#define CONVD   6144
#define NH      64
#define HP      64
#define SN      128
#define NG      8
#define CSZ     256
#define NCH     16
#define DTOFF   10240

// ---------------- scratch ----------------
__device__ float g_proj[(size_t)SS * PROJD];
__device__ float g_hconv[(size_t)SS * CONVD];
__device__ float g_dt2[SS * NH];
__device__ float g_acum[NH * SS];
__device__ float g_y[(size_t)SS * INTERD];
__device__ __nv_bfloat16 g_Apack[(size_t)SS * 3 * INTERD];
__device__ __nv_bfloat16 g_B1[(size_t)PROJPAD * 3 * EMB];
__device__ __nv_bfloat16 g_B2[(size_t)EMB * 3 * INTERD];

// ================= helpers =================
__device__ __forceinline__ uint32_t smem_u32(const void* p) {
    uint32_t a;
    asm("{ .reg .u64 t; cvta.to.shared.u64 t, %1; cvt.u32.u64 %0, t; }" : "=r"(a) : "l"(p));
    return a;
}
__device__ __forceinline__ void cp_async16(uint32_t saddr, const void* g) {
    asm volatile("cp.async.cg.shared.global [%0], [%1], 16;" :: "r"(saddr), "l"(g) : "memory");
}
#define CP_COMMIT() asm volatile("cp.async.commit_group;" ::: "memory")

__device__ __forceinline__ void ldsm_x4(uint32_t addr, uint32_t& r0, uint32_t& r1,
                                        uint32_t& r2, uint32_t& r3) {
    asm volatile("ldmatrix.sync.aligned.m8n8.x4.shared.b16 {%0,%1,%2,%3}, [%4];"
                 : "=r"(r0), "=r"(r1), "=r"(r2), "=r"(r3) : "r"(addr));
}
__device__ __forceinline__ void mma_bf16(float* d, const uint32_t* a, uint32_t b0, uint32_t b1) {
    asm volatile(
        "mma.sync.aligned.m16n8k16.row.col.f32.bf16.bf16.f32 "
        "{%0,%1,%2,%3}, {%4,%5,%6,%7}, {%8,%9}, {%0,%1,%2,%3};"
        : "+f"(d[0]), "+f"(d[1]), "+f"(d[2]), "+f"(d[3])
        : "r"(a[0]), "r"(a[1]), "r"(a[2]), "r"(a[3]), "r"(b0), "r"(b1));
}
__device__ __forceinline__ uint32_t pack_bf2(float x, float y) {
    __nv_bfloat16 a = __float2bfloat16(x);
    __nv_bfloat16 b = __float2bfloat16(y);
    return (uint32_t)__bfloat16_as_ushort(a) | ((uint32_t)__bfloat16_as_ushort(b) << 16);
}

// ================= split-pack (vectorized, row-ranged) =================
__global__ void pack_split(const float* __restrict__ src, __nv_bfloat16* __restrict__ dst,
                           int srcRows, int rowStart, int rowEnd, int K, int mode) {
    const int K8 = K >> 3;
    const size_t total = (size_t)(rowEnd - rowStart) * K8;
    for (size_t v = (size_t)blockIdx.x * 256 + threadIdx.x; v < total;
         v += (size_t)gridDim.x * 256) {
        const int r = rowStart + (int)(v / K8);
        const int k = (int)(v % K8) << 3;
        float x[8];
        if (r < srcRows) {
            const float4 f0 = *(const float4*)(src + (size_t)r * K + k);
            const float4 f1 = *(const float4*)(src + (size_t)r * K + k + 4);
            x[0] = f0.x; x[1] = f0.y; x[2] = f0.z; x[3] = f0.w;
            x[4] = f1.x; x[5] = f1.y; x[6] = f1.z; x[7] = f1.w;
        } else {
#pragma unroll
            for (int i = 0; i < 8; i++) x[i] = 0.f;
        }
        union { __nv_bfloat16 h[8]; uint4 u; } uh, ul;
#pragma unroll
        for (int i = 0; i < 8; i++) {
            uh.h[i] = __float2bfloat16(x[i]);
            ul.h[i] = __float2bfloat16(x[i] - __bfloat162float(uh.h[i]));
        }
        const size_t ro = (size_t)r * 3 * K + k;
        *(uint4*)(dst + ro) = uh.u;
        if (mode == 0) {
            *(uint4*)(dst + ro + K) = ul.u;
            *(uint4*)(dst + ro + 2 * K) = uh.u;
        } else {
            *(uint4*)(dst + ro + K) = uh.u;
            *(uint4*)(dst + ro + 2 * K) = ul.u;
        }
    }
}

// ================= HMMA GEMM: C[M,N] = A[M,K3] * B[N,K3]^T =================
#define GSTAGES 3
#define GSTAGE_BYTES 32768
#define GEMM_DYN_SMEM (GSTAGES * GSTAGE_BYTES)

__device__ __forceinline__ void gemm_load_stage(
    const __nv_bfloat16* __restrict__ A, const __nv_bfloat16* __restrict__ B,
    int K3, int m0, int n0, int tid, uint32_t sb, int stage, int kk) {
    const uint32_t abase = sb + stage * GSTAGE_BYTES;
    const uint32_t bbase = abase + 16384;
    const int k0 = kk * 64;
#pragma unroll
    for (int it = 0; it < 4; it++) {
        const int idx = it * 256 + tid;
        const int row = idx >> 3;
        const int ch = idx & 7;
        const int csw = ch ^ (row & 7);
        cp_async16(abase + row * 128 + csw * 16,
                   A + (size_t)(m0 + row) * K3 + k0 + ch * 8);
    }
#pragma unroll
    for (int it = 0; it < 4; it++) {
        const int idx = it * 256 + tid;
        const int row = idx >> 3;
        const int ch = idx & 7;
        const int csw = ch ^ (row & 7);
        cp_async16(bbase + row * 128 + csw * 16,
                   B + (size_t)(n0 + row) * K3 + k0 + ch * 8);
    }
}

__global__ __launch_bounds__(256, 2)
void tgemm(const __nv_bfloat16* __restrict__ A, const __nv_bfloat16* __restrict__ B,
           float* __restrict__ C, int K3, int Nvalid, int Nstride) {
    extern __shared__ char dynsm[];
    const uint32_t sb = smem_u32(dynsm);
    const int tid = threadIdx.x;
    const int lane = tid & 31;
    const int wid = tid >> 5;
    const int wm = wid & 3;
    const int wn = wid >> 2;

    const int gridM = gridDim.x;
    const int gridN = gridDim.y;
    const int bid = blockIdx.y * gridM + blockIdx.x;
    const int GM = 16;
    const int group = bid / (GM * gridN);
    const int rem = bid - group * (GM * gridN);
    const int m0 = (group * GM + (rem % GM)) * 128;
    const int n0 = (rem / GM) * 128;
    const int nK = K3 >> 6;

    float acc[2][8][4];
#pragma unroll
    for (int i = 0; i < 2; i++)
#pragma unroll
        for (int j = 0; j < 8; j++)
#pragma unroll
            for (int q = 0; q < 4; q++) acc[i][j][q] = 0.f;

    gemm_load_stage(A, B, K3, m0, n0, tid, sb, 0, 0); CP_COMMIT();
    gemm_load_stage(A, B, K3, m0, n0, tid, sb, 1, 1); CP_COMMIT();

    const int a_row = wm * 32 + (lane & 15);
    const int a_chg = lane >> 4;
    const int b_g = lane >> 3;
    const int b_row = wn * 64 + ((b_g >> 1) << 3) + (lane & 7);
    const int b_chg = b_g & 1;

    int buf = 0, nbuf = 2;
    for (int i = 0; i < nK; i++) {
        asm volatile("cp.async.wait_group 1;" ::: "memory");
        __syncthreads();
        if (i + 2 < nK) gemm_load_stage(A, B, K3, m0, n0, tid, sb, nbuf, i + 2);
        CP_COMMIT();

        const uint32_t abase = sb + buf * GSTAGE_BYTES;
        const uint32_t bbase = abase + 16384;
#pragma unroll
        for (int kk = 0; kk < 4; kk++) {
            uint32_t af[2][4];
#pragma unroll
            for (int mi = 0; mi < 2; mi++) {
                const int row = a_row + mi * 16;
                const int ch = kk * 2 + a_chg;
                const int csw = ch ^ (row & 7);
                ldsm_x4(abase + row * 128 + csw * 16,
                        af[mi][0], af[mi][1], af[mi][2], af[mi][3]);
            }
            uint32_t bf[4][4];
#pragma unroll
            for (int nb = 0; nb < 4; nb++) {
                const int row = b_row + nb * 16;
                const int ch = kk * 2 + b_chg;
                const int csw = ch ^ (row & 7);
                ldsm_x4(bbase + row * 128 + csw * 16,
                        bf[nb][0], bf[nb][1], bf[nb][2], bf[nb][3]);
            }
#pragma unroll
            for (int mi = 0; mi < 2; mi++)
#pragma unroll
                for (int nb = 0; nb < 4; nb++) {
                    mma_bf16(acc[mi][nb * 2 + 0], af[mi], bf[nb][0], bf[nb][1]);
                    mma_bf16(acc[mi][nb * 2 + 1], af[mi], bf[nb][2], bf[nb][3]);
                }
        }
        buf = (buf + 1 == GSTAGES) ? 0 : buf + 1;
        nbuf = (nbuf + 1 == GSTAGES) ? 0 : nbuf + 1;
    }

    const int erow = (lane >> 2);
    const int ecol = (lane & 3) << 1;
#pragma unroll
    for (int mi = 0; mi < 2; mi++) {
        const int r = m0 + wm * 32 + mi * 16 + erow;
#pragma unroll
        for (int f = 0; f < 8; f++) {
            const int c = n0 + wn * 64 + (f >> 1) * 16 + (f & 1) * 8 + ecol;
            if (c < Nvalid) {
                *(float2*)(C + (size_t)r * Nstride + c) =
                    make_float2(acc[mi][f][0], acc[mi][f][1]);
                *(float2*)(C + (size_t)(r + 8) * Nstride + c) =
                    make_float2(acc[mi][f][2], acc[mi][f][3]);
            }
        }
    }
}

// ---------------- depthwise causal conv (K=4) + bias + silu, 8 t/thread ----------------
__global__ void conv_silu_kernel(const float* __restrict__ cw, const float* __restrict__ cb) {
    const int c = blockIdx.x * 256 + threadIdx.x;
    const int tb = blockIdx.y * 8;
    const float w0 = cw[c * 4 + 0], w1 = cw[c * 4 + 1],
                w2 = cw[c * 4 + 2], w3 = cw[c * 4 + 3];
    const float bias = cb[c];
    float v[11];
#pragma unroll
    for (int k = 0; k < 11; k++) {
        const int tt = tb - 3 + k;
        v[k] = (tt >= 0) ? g_proj[(size_t)tt * PROJD + INTERD + c] : 0.f;
    }
#pragma unroll
    for (int j = 0; j < 8; j++) {
        const float a = bias + v[j] * w0 + v[j + 1] * w1 + v[j + 2] * w2 + v[j + 3] * w3;
        g_hconv[(size_t)(tb + j) * CONVD + c] = a / (1.f + __expf(-a));
    }
}

// ---------------- fused softplus(dt)+cumsum per (chunk, head) ----------------
__global__ void dtacum_kernel(const float* __restrict__ dt_bias,
                              const float* __restrict__ A_log) {
    const int chunk = blockIdx.x;
    const int h = blockIdx.y;
    const int tid = threadIdx.x;
    const float Ah = -expf(A_log[h]);
    const float bias = dt_bias[h];
    __shared__ float s[CSZ];
    const int t = chunk * CSZ + tid;
    const float x = g_proj[(size_t)t * PROJD + DTOFF + h] + bias;
    const float dt2 = (x > 20.f) ? x : log1pf(expf(x));
    g_dt2[t * NH + h] = dt2;
    s[tid] = Ah * dt2;
    for (int off = 1; off < CSZ; off <<= 1) {
        __syncthreads();
        const float v = (tid >= off) ? s[tid - off] : 0.f;
        __syncthreads();
        s[tid] += v;
    }
    g_acum[h * SS + t] = s[tid];
}

// ================= SSD via HMMA (split-bf16 3-term), 512 threads =================
// One CTA per (chunk, head): 16 warps x 16 i-rows = 256 rows, 4 j-tiles of 64.
// smem: Chi/Clo 256x128 (64KB each); B hi/lo 64x128 (16KB each) overlapped with
// Gw hi (32KB); Gw lo 32KB; X hi/lo transposed 64x64 (8KB each); acs 1KB.
#define S_CHI 0
#define S_CLO 65536
#define S_GWH 131072
#define S_BHI 131072
#define S_BLO 147456
#define S_GWL 163840
#define S_XHI 196608
#define S_XLO 204800
#define S_ACS 212992
#define SSD_DYN_SMEM (S_ACS + 1024)

__global__ __launch_bounds__(512, 1)
void ssd_hmma(const float* __restrict__ Dp) {
    extern __shared__ char sm[];
    const uint32_t sb = smem_u32(sm);
    float* acs = (float*)(sm + S_ACS);
    const int tid = threadIdx.x;
    const int lane = tid & 31;
    const int w = tid >> 5;              // 0..15
    const int chunk = blockIdx.x;
    const int h = blockIdx.y;
    const int t0 = chunk * CSZ;
    const int grp = h & 7;
    const int Bbase = INTERD + grp * SN;
    const int Cbase = INTERD + NG * SN + grp * SN;
    const int i0 = w * 16;               // 16 i-rows per warp

    if (tid < CSZ) acs[tid] = g_acum[h * SS + t0 + tid];

    // load + split C: 256 rows x 128 n (256B rows, 16 chunks, swizzled)
#pragma unroll 4
    for (int it = 0; it < 8; it++) {
        const int u = it * 512 + tid;
        const int i = u >> 4;
        const int nb = u & 15;
        const float* src = g_hconv + (size_t)(t0 + i) * CONVD + Cbase + nb * 8;
        const float4 f0 = *(const float4*)(src);
        const float4 f1 = *(const float4*)(src + 4);
        const float xv[8] = {f0.x, f0.y, f0.z, f0.w, f1.x, f1.y, f1.z, f1.w};
        union { __nv_bfloat16 b[8]; uint4 u4; } hh, ll;
#pragma unroll
        for (int q = 0; q < 8; q++) {
            hh.b[q] = __float2bfloat16(xv[q]);
            ll.b[q] = __float2bfloat16(xv[q] - __bfloat162float(hh.b[q]));
        }
        const int csw = nb ^ (i & 7);
        *(uint4*)(sm + S_CHI + i * 256 + csw * 16) = hh.u4;
        *(uint4*)(sm + S_CLO + i * 256 + csw * 16) = ll.u4;
    }
    __syncthreads();
    const float alast = acs[CSZ - 1];
    const int ro = lane >> 2;
    const int co = (lane & 3) * 2;
    const int r1 = i0 + ro;              // this thread's accumulator i-rows
    const int r2 = r1 + 8;
    const float a1 = acs[r1];
    const float a2 = acs[r2];

    float yacc[8][4];
#pragma unroll
    for (int nb = 0; nb < 8; nb++)
#pragma unroll
        for (int q = 0; q < 4; q++) yacc[nb][q] = 0.f;

    for (int jt = 0; jt < 4; jt++) {
        const int jb = jt * 64;
        // load + split B tile: 64 rows x 128 n
#pragma unroll
        for (int it = 0; it < 2; it++) {
            const int u = it * 512 + tid;
            const int j = u >> 4;
            const int nb = u & 15;
            const float* src = g_hconv + (size_t)(t0 + jb + j) * CONVD + Bbase + nb * 8;
            const float4 f0 = *(const float4*)(src);
            const float4 f1 = *(const float4*)(src + 4);
            const float xv[8] = {f0.x, f0.y, f0.z, f0.w, f1.x, f1.y, f1.z, f1.w};
            union { __nv_bfloat16 b[8]; uint4 u4; } hh, ll;
#pragma unroll
            for (int q = 0; q < 8; q++) {
                hh.b[q] = __float2bfloat16(xv[q]);
                ll.b[q] = __float2bfloat16(xv[q] - __bfloat162float(hh.b[q]));
            }
            const int csw = nb ^ (j & 7);
            *(uint4*)(sm + S_BHI + j * 256 + csw * 16) = hh.u4;
            *(uint4*)(sm + S_BLO + j * 256 + csw * 16) = ll.u4;
        }
        // load + split X (hid*dt2), store TRANSPOSED [p][j] (128B rows, swizzled)
#pragma unroll
        for (int it = 0; it < 2; it++) {
            const int u = it * 512 + tid;
            const int j = u >> 4;
            const int pb = (u & 15) * 4;
            const int tj = t0 + jb + j;
            float4 v = *(const float4*)(g_hconv + (size_t)tj * CONVD + h * HP + pb);
            const float sc = g_dt2[tj * NH + h];
            const float xv[4] = {v.x * sc, v.y * sc, v.z * sc, v.w * sc};
            const int wo = (j * 2) & 15;
            const int chn = j >> 3;
#pragma unroll
            for (int q = 0; q < 4; q++) {
                const int p = pb + q;
                const __nv_bfloat16 hb = __float2bfloat16(xv[q]);
                const __nv_bfloat16 lb = __float2bfloat16(xv[q] - __bfloat162float(hb));
                const uint32_t ad = p * 128 + ((chn ^ (p & 7)) << 4) + wo;
                *(__nv_bfloat16*)(sm + S_XHI + ad) = hb;
                *(__nv_bfloat16*)(sm + S_XLO + ad) = lb;
            }
        }
        __syncthreads();

        // ---- stage 1: Gram (16 i-rows per warp x 64 j), K = 128 x 3 terms ----
        float gacc[8][4];
#pragma unroll
        for (int nb = 0; nb < 8; nb++)
#pragma unroll
            for (int q = 0; q < 4; q++) gacc[nb][q] = 0.f;

        for (int term = 0; term < 3; term++) {
            const uint32_t Ab = sb + ((term == 1) ? S_CLO : S_CHI);
            const uint32_t Bb = sb + ((term == 2) ? S_BLO : S_BHI);
#pragma unroll
            for (int ks = 0; ks < 8; ks++) {
                uint32_t af[4];
                {
                    const int row = i0 + (lane & 15);
                    const int ch = 2 * ks + (lane >> 4);
                    const int csw = ch ^ (row & 7);
                    ldsm_x4(Ab + row * 256 + csw * 16, af[0], af[1], af[2], af[3]);
                }
#pragma unroll
                for (int q = 0; q < 4; q++) {
                    const int bg = lane >> 3;
                    const int brow = q * 16 + ((bg >> 1) << 3) + (lane & 7);
                    const int bch = 2 * ks + (bg & 1);
                    const int bcsw = bch ^ (brow & 7);
                    uint32_t b0, b1, b2, b3;
                    ldsm_x4(Bb + brow * 256 + bcsw * 16, b0, b1, b2, b3);
                    mma_bf16(gacc[q * 2 + 0], af, b0, b1);
                    mma_bf16(gacc[q * 2 + 1], af, b2, b3);
                }
            }
        }

        // ---- weight in-register (SAFE two-exp form: all used exponents <= 0) ----
#pragma unroll
        for (int nb = 0; nb < 8; nb++) {
            const int cb = (nb >> 1) * 16 + (nb & 1) * 8 + co;
            const int jg = jb + cb;
            const float aj0 = acs[jg];
            const float aj1 = acs[jg + 1];
            float wv;
            wv = __expf(a1 - aj0 + alast) + ((jg     <= r1) ? __expf(a1 - aj0) : 0.f);
            gacc[nb][0] *= wv;
            wv = __expf(a1 - aj1 + alast) + ((jg + 1 <= r1) ? __expf(a1 - aj1) : 0.f);
            gacc[nb][1] *= wv;
            wv = __expf(a2 - aj0 + alast) + ((jg     <= r2) ? __expf(a2 - aj0) : 0.f);
            gacc[nb][2] *= wv;
            wv = __expf(a2 - aj1 + alast) + ((jg + 1 <= r2) ? __expf(a2 - aj1) : 0.f);
            gacc[nb][3] *= wv;
        }
        __syncthreads();   // all B reads complete before Gw overwrites the B region

        // ---- store Gw hi/lo to smem (128B rows, swizzled) ----
#pragma unroll
        for (int nb = 0; nb < 8; nb++) {
            const int c = (nb >> 1) * 16 + (nb & 1) * 8 + co;
            const int chn = c >> 3;
            const int wo = (c * 2) & 15;
            const uint32_t ad1 = r1 * 128 + ((chn ^ (r1 & 7)) << 4) + wo;
            const uint32_t ad2 = r2 * 128 + ((chn ^ (r2 & 7)) << 4) + wo;
            *(uint32_t*)(sm + S_GWH + ad1) = pack_bf2(gacc[nb][0], gacc[nb][1]);
            *(uint32_t*)(sm + S_GWL + ad1) = pack_bf2(
                gacc[nb][0] - __bfloat162float(__float2bfloat16(gacc[nb][0])),
                gacc[nb][1] - __bfloat162float(__float2bfloat16(gacc[nb][1])));
            *(uint32_t*)(sm + S_GWH + ad2) = pack_bf2(gacc[nb][2], gacc[nb][3]);
            *(uint32_t*)(sm + S_GWL + ad2) = pack_bf2(
                gacc[nb][2] - __bfloat162float(__float2bfloat16(gacc[nb][2])),
                gacc[nb][3] - __bfloat162float(__float2bfloat16(gacc[nb][3])));
        }
        __syncthreads();

        // ---- stage 2: Y += Gw @ X^T, K = 64 x 3 terms ----
        for (int term = 0; term < 3; term++) {
            const uint32_t Ab = sb + ((term == 1) ? S_GWL : S_GWH);
            const uint32_t Bb = sb + ((term == 2) ? S_XLO : S_XHI);
#pragma unroll
            for (int ks = 0; ks < 4; ks++) {
                uint32_t af[4];
                {
                    const int row = i0 + (lane & 15);
                    const int ch = 2 * ks + (lane >> 4);
                    const int csw = ch ^ (row & 7);
                    ldsm_x4(Ab + row * 128 + csw * 16, af[0], af[1], af[2], af[3]);
                }
#pragma unroll
                for (int q = 0; q < 4; q++) {
                    const int bg = lane >> 3;
                    const int brow = q * 16 + ((bg >> 1) << 3) + (lane & 7);
                    const int bch = 2 * ks + (bg & 1);
                    const int bcsw = bch ^ (brow & 7);
                    uint32_t b0, b1, b2, b3;
                    ldsm_x4(Bb + brow * 128 + bcsw * 16, b0, b1, b2, b3);
                    mma_bf16(yacc[q * 2 + 0], af, b0, b1);
                    mma_bf16(yacc[q * 2 + 1], af, b2, b3);
                }
            }
        }
        __syncthreads();   // stage2 reads done before next jt overwrites B/X/Gw
    }

    // ---- epilogue: D residual + store Y ----
    const float Dh = Dp[h];
    const int gr1 = t0 + r1;
    const int gr2 = t0 + r2;
#pragma unroll
    for (int nb = 0; nb < 8; nb++) {
        const int p = (nb >> 1) * 16 + (nb & 1) * 8 + co;
        const float2 h1 = *(const float2*)(g_hconv + (size_t)gr1 * CONVD + h * HP + p);
        const float2 h2 = *(const float2*)(g_hconv + (size_t)gr2 * CONVD + h * HP + p);
        *(float2*)(g_y + (size_t)gr1 * INTERD + h * HP + p) =
            make_float2(yacc[nb][0] + Dh * h1.x, yacc[nb][1] + Dh * h1.y);
        *(float2*)(g_y + (size_t)gr2 * INTERD + h * HP + p) =
            make_float2(yacc[nb][2] + Dh * h2.x, yacc[nb][3] + Dh * h2.y);
    }
}

// ---------------- gate silu + RMSNorm + split-bf16 A-pack (fused) ----------------
__global__ void norm_pack_kernel(const float* __restrict__ norm_w) {
    const int t = blockIdx.x;
    const int tid = threadIdx.x;
    __shared__ float red[256];
    __shared__ float yg_s[INTERD];
    float local = 0.f;
    for (int c = tid; c < INTERD; c += 256) {
        const float g = g_proj[(size_t)t * PROJD + c];
        const float yv = g_y[(size_t)t * INTERD + c];
        const float yg = yv * (g / (1.f + __expf(-g)));
        yg_s[c] = yg;
        local += yg * yg;
    }
    red[tid] = local;
    __syncthreads();
    for (int s = 128; s > 0; s >>= 1) {
        if (tid < s) red[tid] += red[tid + s];
        __syncthreads();
    }
    const float rstd = rsqrtf(red[0] / (float)INTERD + 1e-6f);
    __nv_bfloat16* dst = g_Apack + (size_t)t * 3 * INTERD;
    for (int c = tid * 4; c < INTERD; c += 1024) {
        union { __nv_bfloat16 h[4]; uint2 u; } uh, ul;
#pragma unroll
        for (int i = 0; i < 4; i++) {
            const float v = norm_w[c + i] * yg_s[c + i] * rstd;
            uh.h[i] = __float2bfloat16(v);
            ul.h[i] = __float2bfloat16(v - __bfloat162float(uh.h[i]));
        }
        *(uint2*)(dst + c) = uh.u;
        *(uint2*)(dst + INTERD + c) = ul.u;
        *(uint2*)(dst + 2 * INTERD + c) = uh.u;
    }
}

// ---------------- launch ----------------
extern "C" void kernel_launch(void* const* d_in, const int* in_sizes, int n_in,
                              void* d_out, int out_size) {
    (void)in_sizes; (void)n_in; (void)out_size;
    const float* x       = (const float*)d_in[0];
    const float* w_in    = (const float*)d_in[1];
    const float* conv_w  = (const float*)d_in[2];
    const float* conv_b  = (const float*)d_in[3];
    const float* dt_bias = (const float*)d_in[4];
    const float* A_log   = (const float*)d_in[5];
    const float* Dv      = (const float*)d_in[6];
    const float* norm_w  = (const float*)d_in[7];
    const float* w_out   = (const float*)d_in[8];
    float* out = (float*)d_out;

    float* p_proj = nullptr;
    __nv_bfloat16* p_Apack = nullptr;
    __nv_bfloat16* p_B1 = nullptr;
    __nv_bfloat16* p_B2 = nullptr;
    cudaGetSymbolAddress((void**)&p_proj, g_proj);
    cudaGetSymbolAddress((void**)&p_Apack, g_Apack);
    cudaGetSymbolAddress((void**)&p_B1, g_B1);
    cudaGetSymbolAddress((void**)&p_B2, g_B2);

    cudaFuncSetAttribute(tgemm, cudaFuncAttributeMaxDynamicSharedMemorySize, GEMM_DYN_SMEM);
    cudaFuncSetAttribute(ssd_hmma, cudaFuncAttributeMaxDynamicSharedMemorySize, SSD_DYN_SMEM);

    // --- GEMM1 packs (split so tgemm is the 4th launch for ncu) ---
    pack_split<<<2048, 256>>>(x, p_Apack, SS, 0, SS, EMB, 0);
    pack_split<<<2048, 256>>>(w_in, p_B1, PROJD, 0, PROJPAD / 2, EMB, 1);
    pack_split<<<2048, 256>>>(w_in, p_B1, PROJD, PROJPAD / 2, PROJPAD, EMB, 1);
    // --- GEMM1: proj = X @ W_in^T ---
    tgemm<<<dim3(SS / 128, PROJPAD / 128), 256, GEMM_DYN_SMEM>>>(
        p_Apack, p_B1, p_proj, 3 * EMB, PROJD, PROJD);

    // --- elementwise / scan stages ---
    conv_silu_kernel<<<dim3(CONVD / 256, SS / 8), 256>>>(conv_w, conv_b);
    dtacum_kernel<<<dim3(NCH, NH), CSZ>>>(dt_bias, A_log);
    ssd_hmma<<<dim3(NCH, NH), 512, SSD_DYN_SMEM>>>(Dv);
    norm_pack_kernel<<<SS, 256>>>(norm_w);

    // --- GEMM2: out = normed @ W_out^T ---
    pack_split<<<2048, 256>>>(w_out, p_B2, EMB, 0, EMB, INTERD, 1);
    tgemm<<<dim3(SS / 128, EMB / 128), 256, GEMM_DYN_SMEM>>>(
        p_Apack, p_B2, out, 3 * INTERD, EMB, EMB);
}

// round 10
// speedup vs baseline: 1.0536x; 1.0335x over previous
#include <cuda_runtime.h>
#include <cuda_bf16.h>
#include <cstdint>
#include <cstddef>

// ---------------- problem constants ----------------
#define SS      4096
#define EMB     2048
#define PROJD   10304
#define PROJPAD 10368
#define INTERD  4096
#define CONVD   6144
#define NH      64
#define HP      64
#define SN      128
#define NG      8
#define CSZ     256
#define NCH     16
#define DTOFF   10240
#define BCW     2048      // width of pre-split B/C region (CONVD - INTERD)

// ---------------- scratch ----------------
__device__ float g_proj[(size_t)SS * PROJD];
__device__ float g_hconv[(size_t)SS * CONVD];   // only cols < INTERD written/used now
__device__ float g_dt2[SS * NH];
__device__ float g_acum[NH * SS];
__device__ float g_y[(size_t)SS * INTERD];
__device__ __nv_bfloat16 g_bch[(size_t)SS * BCW];   // pre-split B/C hi
__device__ __nv_bfloat16 g_bcl[(size_t)SS * BCW];   // pre-split B/C lo
__device__ __nv_bfloat16 g_Apack[(size_t)SS * 3 * INTERD];
__device__ __nv_bfloat16 g_B1[(size_t)PROJPAD * 3 * EMB];
__device__ __nv_bfloat16 g_B2[(size_t)EMB * 3 * INTERD];

// ================= helpers =================
__device__ __forceinline__ uint32_t smem_u32(const void* p) {
    uint32_t a;
    asm("{ .reg .u64 t; cvta.to.shared.u64 t, %1; cvt.u32.u64 %0, t; }" : "=r"(a) : "l"(p));
    return a;
}
__device__ __forceinline__ void cp_async16(uint32_t saddr, const void* g) {
    asm volatile("cp.async.cg.shared.global [%0], [%1], 16;" :: "r"(saddr), "l"(g) : "memory");
}
#define CP_COMMIT() asm volatile("cp.async.commit_group;" ::: "memory")

__device__ __forceinline__ void ldsm_x4(uint32_t addr, uint32_t& r0, uint32_t& r1,
                                        uint32_t& r2, uint32_t& r3) {
    asm volatile("ldmatrix.sync.aligned.m8n8.x4.shared.b16 {%0,%1,%2,%3}, [%4];"
                 : "=r"(r0), "=r"(r1), "=r"(r2), "=r"(r3) : "r"(addr));
}
__device__ __forceinline__ void mma_bf16(float* d, const uint32_t* a, uint32_t b0, uint32_t b1) {
    asm volatile(
        "mma.sync.aligned.m16n8k16.row.col.f32.bf16.bf16.f32 "
        "{%0,%1,%2,%3}, {%4,%5,%6,%7}, {%8,%9}, {%0,%1,%2,%3};"
        : "+f"(d[0]), "+f"(d[1]), "+f"(d[2]), "+f"(d[3])
        : "r"(a[0]), "r"(a[1]), "r"(a[2]), "r"(a[3]), "r"(b0), "r"(b1));
}
__device__ __forceinline__ uint32_t pack_bf2(float x, float y) {
    __nv_bfloat16 a = __float2bfloat16(x);
    __nv_bfloat16 b = __float2bfloat16(y);
    return (uint32_t)__bfloat16_as_ushort(a) | ((uint32_t)__bfloat16_as_ushort(b) << 16);
}

// ================= split-pack (vectorized, row-ranged) =================
__global__ void pack_split(const float* __restrict__ src, __nv_bfloat16* __restrict__ dst,
                           int srcRows, int rowStart, int rowEnd, int K, int mode) {
    const int K8 = K >> 3;
    const size_t total = (size_t)(rowEnd - rowStart) * K8;
    for (size_t v = (size_t)blockIdx.x * 256 + threadIdx.x; v < total;
         v += (size_t)gridDim.x * 256) {
        const int r = rowStart + (int)(v / K8);
        const int k = (int)(v % K8) << 3;
        float x[8];
        if (r < srcRows) {
            const float4 f0 = *(const float4*)(src + (size_t)r * K + k);
            const float4 f1 = *(const float4*)(src + (size_t)r * K + k + 4);
            x[0] = f0.x; x[1] = f0.y; x[2] = f0.z; x[3] = f0.w;
            x[4] = f1.x; x[5] = f1.y; x[6] = f1.z; x[7] = f1.w;
        } else {
#pragma unroll
            for (int i = 0; i < 8; i++) x[i] = 0.f;
        }
        union { __nv_bfloat16 h[8]; uint4 u; } uh, ul;
#pragma unroll
        for (int i = 0; i < 8; i++) {
            uh.h[i] = __float2bfloat16(x[i]);
            ul.h[i] = __float2bfloat16(x[i] - __bfloat162float(uh.h[i]));
        }
        const size_t ro = (size_t)r * 3 * K + k;
        *(uint4*)(dst + ro) = uh.u;
        if (mode == 0) {
            *(uint4*)(dst + ro + K) = ul.u;
            *(uint4*)(dst + ro + 2 * K) = uh.u;
        } else {
            *(uint4*)(dst + ro + K) = uh.u;
            *(uint4*)(dst + ro + 2 * K) = ul.u;
        }
    }
}

// ================= HMMA GEMM: C[M,N] = A[M,K3] * B[N,K3]^T =================
#define GSTAGES 3
#define GSTAGE_BYTES 32768
#define GEMM_DYN_SMEM (GSTAGES * GSTAGE_BYTES)

__device__ __forceinline__ void gemm_load_stage(
    const __nv_bfloat16* __restrict__ A, const __nv_bfloat16* __restrict__ B,
    int K3, int m0, int n0, int tid, uint32_t sb, int stage, int kk) {
    const uint32_t abase = sb + stage * GSTAGE_BYTES;
    const uint32_t bbase = abase + 16384;
    const int k0 = kk * 64;
#pragma unroll
    for (int it = 0; it < 4; it++) {
        const int idx = it * 256 + tid;
        const int row = idx >> 3;
        const int ch = idx & 7;
        const int csw = ch ^ (row & 7);
        cp_async16(abase + row * 128 + csw * 16,
                   A + (size_t)(m0 + row) * K3 + k0 + ch * 8);
    }
#pragma unroll
    for (int it = 0; it < 4; it++) {
        const int idx = it * 256 + tid;
        const int row = idx >> 3;
        const int ch = idx & 7;
        const int csw = ch ^ (row & 7);
        cp_async16(bbase + row * 128 + csw * 16,
                   B + (size_t)(n0 + row) * K3 + k0 + ch * 8);
    }
}

__global__ __launch_bounds__(256, 2)
void tgemm(const __nv_bfloat16* __restrict__ A, const __nv_bfloat16* __restrict__ B,
           float* __restrict__ C, int K3, int Nvalid, int Nstride) {
    extern __shared__ char dynsm[];
    const uint32_t sb = smem_u32(dynsm);
    const int tid = threadIdx.x;
    const int lane = tid & 31;
    const int wid = tid >> 5;
    const int wm = wid & 3;
    const int wn = wid >> 2;

    const int gridM = gridDim.x;
    const int gridN = gridDim.y;
    const int bid = blockIdx.y * gridM + blockIdx.x;
    const int GM = 16;
    const int group = bid / (GM * gridN);
    const int rem = bid - group * (GM * gridN);
    const int m0 = (group * GM + (rem % GM)) * 128;
    const int n0 = (rem / GM) * 128;
    const int nK = K3 >> 6;

    float acc[2][8][4];
#pragma unroll
    for (int i = 0; i < 2; i++)
#pragma unroll
        for (int j = 0; j < 8; j++)
#pragma unroll
            for (int q = 0; q < 4; q++) acc[i][j][q] = 0.f;

    gemm_load_stage(A, B, K3, m0, n0, tid, sb, 0, 0); CP_COMMIT();
    gemm_load_stage(A, B, K3, m0, n0, tid, sb, 1, 1); CP_COMMIT();

    const int a_row = wm * 32 + (lane & 15);
    const int a_chg = lane >> 4;
    const int b_g = lane >> 3;
    const int b_row = wn * 64 + ((b_g >> 1) << 3) + (lane & 7);
    const int b_chg = b_g & 1;

    int buf = 0, nbuf = 2;
    for (int i = 0; i < nK; i++) {
        asm volatile("cp.async.wait_group 1;" ::: "memory");
        __syncthreads();
        if (i + 2 < nK) gemm_load_stage(A, B, K3, m0, n0, tid, sb, nbuf, i + 2);
        CP_COMMIT();

        const uint32_t abase = sb + buf * GSTAGE_BYTES;
        const uint32_t bbase = abase + 16384;
#pragma unroll
        for (int kk = 0; kk < 4; kk++) {
            uint32_t af[2][4];
#pragma unroll
            for (int mi = 0; mi < 2; mi++) {
                const int row = a_row + mi * 16;
                const int ch = kk * 2 + a_chg;
                const int csw = ch ^ (row & 7);
                ldsm_x4(abase + row * 128 + csw * 16,
                        af[mi][0], af[mi][1], af[mi][2], af[mi][3]);
            }
            uint32_t bf[4][4];
#pragma unroll
            for (int nb = 0; nb < 4; nb++) {
                const int row = b_row + nb * 16;
                const int ch = kk * 2 + b_chg;
                const int csw = ch ^ (row & 7);
                ldsm_x4(bbase + row * 128 + csw * 16,
                        bf[nb][0], bf[nb][1], bf[nb][2], bf[nb][3]);
            }
#pragma unroll
            for (int mi = 0; mi < 2; mi++)
#pragma unroll
                for (int nb = 0; nb < 4; nb++) {
                    mma_bf16(acc[mi][nb * 2 + 0], af[mi], bf[nb][0], bf[nb][1]);
                    mma_bf16(acc[mi][nb * 2 + 1], af[mi], bf[nb][2], bf[nb][3]);
                }
        }
        buf = (buf + 1 == GSTAGES) ? 0 : buf + 1;
        nbuf = (nbuf + 1 == GSTAGES) ? 0 : nbuf + 1;
    }

    const int erow = (lane >> 2);
    const int ecol = (lane & 3) << 1;
#pragma unroll
    for (int mi = 0; mi < 2; mi++) {
        const int r = m0 + wm * 32 + mi * 16 + erow;
#pragma unroll
        for (int f = 0; f < 8; f++) {
            const int c = n0 + wn * 64 + (f >> 1) * 16 + (f & 1) * 8 + ecol;
            if (c < Nvalid) {
                *(float2*)(C + (size_t)r * Nstride + c) =
                    make_float2(acc[mi][f][0], acc[mi][f][1]);
                *(float2*)(C + (size_t)(r + 8) * Nstride + c) =
                    make_float2(acc[mi][f][2], acc[mi][f][3]);
            }
        }
    }
}

// -------- depthwise causal conv (K=4) + bias + silu, 8 t/thread --------
// cols < INTERD: write fp32 hconv (hidden, needed fp32 for X-scale/epilogue)
// cols >= INTERD (B/C region): write pre-split bf16 hi/lo instead
__global__ void conv_silu_kernel(const float* __restrict__ cw, const float* __restrict__ cb) {
    const int c = blockIdx.x * 256 + threadIdx.x;
    const int tb = blockIdx.y * 8;
    const float w0 = cw[c * 4 + 0], w1 = cw[c * 4 + 1],
                w2 = cw[c * 4 + 2], w3 = cw[c * 4 + 3];
    const float bias = cb[c];
    float v[11];
#pragma unroll
    for (int k = 0; k < 11; k++) {
        const int tt = tb - 3 + k;
        v[k] = (tt >= 0) ? g_proj[(size_t)tt * PROJD + INTERD + c] : 0.f;
    }
    if (c < INTERD) {
#pragma unroll
        for (int j = 0; j < 8; j++) {
            const float a = bias + v[j] * w0 + v[j + 1] * w1 + v[j + 2] * w2 + v[j + 3] * w3;
            g_hconv[(size_t)(tb + j) * CONVD + c] = a / (1.f + __expf(-a));
        }
    } else {
        const int cc = c - INTERD;
#pragma unroll
        for (int j = 0; j < 8; j++) {
            const float a = bias + v[j] * w0 + v[j + 1] * w1 + v[j + 2] * w2 + v[j + 3] * w3;
            const float y = a / (1.f + __expf(-a));
            const __nv_bfloat16 hb = __float2bfloat16(y);
            g_bch[(size_t)(tb + j) * BCW + cc] = hb;
            g_bcl[(size_t)(tb + j) * BCW + cc] =
                __float2bfloat16(y - __bfloat162float(hb));
        }
    }
}

// ---------------- fused softplus(dt)+cumsum per (chunk, head) ----------------
__global__ void dtacum_kernel(const float* __restrict__ dt_bias,
                              const float* __restrict__ A_log) {
    const int chunk = blockIdx.x;
    const int h = blockIdx.y;
    const int tid = threadIdx.x;
    const float Ah = -expf(A_log[h]);
    const float bias = dt_bias[h];
    __shared__ float s[CSZ];
    const int t = chunk * CSZ + tid;
    const float x = g_proj[(size_t)t * PROJD + DTOFF + h] + bias;
    const float dt2 = (x > 20.f) ? x : log1pf(expf(x));
    g_dt2[t * NH + h] = dt2;
    s[tid] = Ah * dt2;
    for (int off = 1; off < CSZ; off <<= 1) {
        __syncthreads();
        const float v = (tid >= off) ? s[tid - off] : 0.f;
        __syncthreads();
        s[tid] += v;
    }
    g_acum[h * SS + t] = s[tid];
}

// ================= SSD via HMMA (split-bf16 3-term), R6 structure + cp.async =================
// One CTA per (chunk, head): 8 warps x 32 i-rows = 256 rows, 4 j-tiles of 64.
// C and B tiles cp.async'd directly from pre-split g_bch/g_bcl (no in-kernel convert).
#define S_CHI 0
#define S_CLO 65536
#define S_GWH 131072
#define S_BHI 131072
#define S_BLO 147456
#define S_GWL 163840
#define S_XHI 196608
#define S_XLO 204800
#define S_ACS 212992
#define SSD_DYN_SMEM (S_ACS + 1024)

__global__ __launch_bounds__(256, 1)
void ssd_hmma(const float* __restrict__ Dp) {
    extern __shared__ char sm[];
    const uint32_t sb = smem_u32(sm);
    float* acs = (float*)(sm + S_ACS);
    const int tid = threadIdx.x;
    const int lane = tid & 31;
    const int w = tid >> 5;
    const int chunk = blockIdx.x;
    const int h = blockIdx.y;
    const int t0 = chunk * CSZ;
    const int grp = h & 7;
    const int Bcol = grp * SN;            // within pre-split BCW array
    const int Ccol = NG * SN + grp * SN;
    const int i0 = w * 32;

    // issue C tile loads: 256 rows x 128 n bf16 hi/lo (16B chunks, swizzled)
#pragma unroll 4
    for (int it = 0; it < 16; it++) {
        const int u = it * 256 + tid;
        const int i = u >> 4;
        const int nb = u & 15;
        const uint32_t dsw = i * 256 + ((nb ^ (i & 7)) << 4);
        const size_t gsrc = (size_t)(t0 + i) * BCW + Ccol + nb * 8;
        cp_async16(sb + S_CHI + dsw, g_bch + gsrc);
        cp_async16(sb + S_CLO + dsw, g_bcl + gsrc);
    }
    CP_COMMIT();

    acs[tid] = g_acum[h * SS + t0 + tid];

    float yacc[2][8][4];
#pragma unroll
    for (int mi = 0; mi < 2; mi++)
#pragma unroll
        for (int nb = 0; nb < 8; nb++)
#pragma unroll
            for (int q = 0; q < 4; q++) yacc[mi][nb][q] = 0.f;

    // constants needed after first sync
    const int ro = lane >> 2;
    const int co = (lane & 3) * 2;

    for (int jt = 0; jt < 4; jt++) {
        const int jb = jt * 64;
        // issue B tile loads: 64 rows x 128 n bf16 hi/lo
#pragma unroll
        for (int it = 0; it < 4; it++) {
            const int u = it * 256 + tid;
            const int j = u >> 4;
            const int nb = u & 15;
            const uint32_t dsw = j * 256 + ((nb ^ (j & 7)) << 4);
            const size_t gsrc = (size_t)(t0 + jb + j) * BCW + Bcol + nb * 8;
            cp_async16(sb + S_BHI + dsw, g_bch + gsrc);
            cp_async16(sb + S_BLO + dsw, g_bcl + gsrc);
        }
        CP_COMMIT();
        // load + split X (hid*dt2), store TRANSPOSED [p][j] (128B rows, swizzled)
#pragma unroll
        for (int it = 0; it < 4; it++) {
            const int u = it * 256 + tid;
            const int j = u >> 4;
            const int pb = (u & 15) * 4;
            const int tj = t0 + jb + j;
            float4 v = *(const float4*)(g_hconv + (size_t)tj * CONVD + h * HP + pb);
            const float sc = g_dt2[tj * NH + h];
            const float xv[4] = {v.x * sc, v.y * sc, v.z * sc, v.w * sc};
            const int wo = (j * 2) & 15;
            const int chn = j >> 3;
#pragma unroll
            for (int q = 0; q < 4; q++) {
                const int p = pb + q;
                const __nv_bfloat16 hb = __float2bfloat16(xv[q]);
                const __nv_bfloat16 lb = __float2bfloat16(xv[q] - __bfloat162float(hb));
                const uint32_t ad = p * 128 + ((chn ^ (p & 7)) << 4) + wo;
                *(__nv_bfloat16*)(sm + S_XHI + ad) = hb;
                *(__nv_bfloat16*)(sm + S_XLO + ad) = lb;
            }
        }
        asm volatile("cp.async.wait_group 0;" ::: "memory");
        __syncthreads();

        const float alast = acs[CSZ - 1];
        const int r1a = i0 + ro;
        const int r1b = r1a + 8;
        const int r2a = r1a + 16;
        const int r2b = r1a + 24;

        // ---- stage 1: Gram (32 i-rows per warp x 64 j), K = 128 x 3 terms ----
        float gacc[2][8][4];
#pragma unroll
        for (int mi = 0; mi < 2; mi++)
#pragma unroll
            for (int nb = 0; nb < 8; nb++)
#pragma unroll
                for (int q = 0; q < 4; q++) gacc[mi][nb][q] = 0.f;

        for (int term = 0; term < 3; term++) {
            const uint32_t Ab = sb + ((term == 1) ? S_CLO : S_CHI);
            const uint32_t Bb = sb + ((term == 2) ? S_BLO : S_BHI);
#pragma unroll
            for (int ks = 0; ks < 8; ks++) {
                uint32_t af[2][4];
#pragma unroll
                for (int mi = 0; mi < 2; mi++) {
                    const int row = i0 + mi * 16 + (lane & 15);
                    const int ch = 2 * ks + (lane >> 4);
                    const int csw = ch ^ (row & 7);
                    ldsm_x4(Ab + row * 256 + csw * 16,
                            af[mi][0], af[mi][1], af[mi][2], af[mi][3]);
                }
#pragma unroll
                for (int q = 0; q < 4; q++) {
                    const int bg = lane >> 3;
                    const int brow = q * 16 + ((bg >> 1) << 3) + (lane & 7);
                    const int bch = 2 * ks + (bg & 1);
                    const int bcsw = bch ^ (brow & 7);
                    uint32_t b0, b1, b2, b3;
                    ldsm_x4(Bb + brow * 256 + bcsw * 16, b0, b1, b2, b3);
                    mma_bf16(gacc[0][q * 2 + 0], af[0], b0, b1);
                    mma_bf16(gacc[0][q * 2 + 1], af[0], b2, b3);
                    mma_bf16(gacc[1][q * 2 + 0], af[1], b0, b1);
                    mma_bf16(gacc[1][q * 2 + 1], af[1], b2, b3);
                }
            }
        }

        // ---- weight in-register (SAFE two-exp form: all used exponents <= 0) ----
#pragma unroll
        for (int mi = 0; mi < 2; mi++) {
            const int r1 = i0 + mi * 16 + ro;
            const int r2 = r1 + 8;
            const float a1 = acs[r1];
            const float a2 = acs[r2];
#pragma unroll
            for (int nb = 0; nb < 8; nb++) {
                const int cb = (nb >> 1) * 16 + (nb & 1) * 8 + co;
                const int jg = jb + cb;
                const float aj0 = acs[jg];
                const float aj1 = acs[jg + 1];
                float wv;
                wv = __expf(a1 - aj0 + alast) + ((jg     <= r1) ? __expf(a1 - aj0) : 0.f);
                gacc[mi][nb][0] *= wv;
                wv = __expf(a1 - aj1 + alast) + ((jg + 1 <= r1) ? __expf(a1 - aj1) : 0.f);
                gacc[mi][nb][1] *= wv;
                wv = __expf(a2 - aj0 + alast) + ((jg     <= r2) ? __expf(a2 - aj0) : 0.f);
                gacc[mi][nb][2] *= wv;
                wv = __expf(a2 - aj1 + alast) + ((jg + 1 <= r2) ? __expf(a2 - aj1) : 0.f);
                gacc[mi][nb][3] *= wv;
            }
        }
        __syncthreads();   // all B reads complete before Gw overwrites the B region

        // ---- store Gw hi/lo to smem (128B rows, swizzled) ----
#pragma unroll
        for (int mi = 0; mi < 2; mi++) {
            const int r1 = i0 + mi * 16 + ro;
            const int r2 = r1 + 8;
#pragma unroll
            for (int nb = 0; nb < 8; nb++) {
                const int c = (nb >> 1) * 16 + (nb & 1) * 8 + co;
                const int chn = c >> 3;
                const int wo = (c * 2) & 15;
                const uint32_t ad1 = r1 * 128 + ((chn ^ (r1 & 7)) << 4) + wo;
                const uint32_t ad2 = r2 * 128 + ((chn ^ (r2 & 7)) << 4) + wo;
                *(uint32_t*)(sm + S_GWH + ad1) = pack_bf2(gacc[mi][nb][0], gacc[mi][nb][1]);
                *(uint32_t*)(sm + S_GWL + ad1) = pack_bf2(
                    gacc[mi][nb][0] - __bfloat162float(__float2bfloat16(gacc[mi][nb][0])),
                    gacc[mi][nb][1] - __bfloat162float(__float2bfloat16(gacc[mi][nb][1])));
                *(uint32_t*)(sm + S_GWH + ad2) = pack_bf2(gacc[mi][nb][2], gacc[mi][nb][3]);
                *(uint32_t*)(sm + S_GWL + ad2) = pack_bf2(
                    gacc[mi][nb][2] - __bfloat162float(__float2bfloat16(gacc[mi][nb][2])),
                    gacc[mi][nb][3] - __bfloat162float(__float2bfloat16(gacc[mi][nb][3])));
            }
        }
        __syncthreads();

        // ---- stage 2: Y += Gw @ X^T, K = 64 x 3 terms ----
        for (int term = 0; term < 3; term++) {
            const uint32_t Ab = sb + ((term == 1) ? S_GWL : S_GWH);
            const uint32_t Bb = sb + ((term == 2) ? S_XLO : S_XHI);
#pragma unroll
            for (int ks = 0; ks < 4; ks++) {
                uint32_t af[2][4];
#pragma unroll
                for (int mi = 0; mi < 2; mi++) {
                    const int row = i0 + mi * 16 + (lane & 15);
                    const int ch = 2 * ks + (lane >> 4);
                    const int csw = ch ^ (row & 7);
                    ldsm_x4(Ab + row * 128 + csw * 16,
                            af[mi][0], af[mi][1], af[mi][2], af[mi][3]);
                }
#pragma unroll
                for (int q = 0; q < 4; q++) {
                    const int bg = lane >> 3;
                    const int brow = q * 16 + ((bg >> 1) << 3) + (lane & 7);
                    const int bch = 2 * ks + (bg & 1);
                    const int bcsw = bch ^ (brow & 7);
                    uint32_t b0, b1, b2, b3;
                    ldsm_x4(Bb + brow * 128 + bcsw * 16, b0, b1, b2, b3);
                    mma_bf16(yacc[0][q * 2 + 0], af[0], b0, b1);
                    mma_bf16(yacc[0][q * 2 + 1], af[0], b2, b3);
                    mma_bf16(yacc[1][q * 2 + 0], af[1], b0, b1);
                    mma_bf16(yacc[1][q * 2 + 1], af[1], b2, b3);
                }
            }
        }
        __syncthreads();   // stage2 reads done before next jt overwrites B/X/Gw
    }

    // ---- epilogue: D residual + store Y ----
    const float Dh = Dp[h];
#pragma unroll
    for (int mi = 0; mi < 2; mi++) {
        const int r1 = t0 + i0 + mi * 16 + ro;
        const int r2 = r1 + 8;
#pragma unroll
        for (int nb = 0; nb < 8; nb++) {
            const int p = (nb >> 1) * 16 + (nb & 1) * 8 + co;
            const float2 h1 = *(const float2*)(g_hconv + (size_t)r1 * CONVD + h * HP + p);
            const float2 h2 = *(const float2*)(g_hconv + (size_t)r2 * CONVD + h * HP + p);
            *(float2*)(g_y + (size_t)r1 * INTERD + h * HP + p) =
                make_float2(yacc[mi][nb][0] + Dh * h1.x, yacc[mi][nb][1] + Dh * h1.y);
            *(float2*)(g_y + (size_t)r2 * INTERD + h * HP + p) =
                make_float2(yacc[mi][nb][2] + Dh * h2.x, yacc[mi][nb][3] + Dh * h2.y);
        }
    }
}

// ---------------- gate silu + RMSNorm + split-bf16 A-pack (fused) ----------------
__global__ void norm_pack_kernel(const float* __restrict__ norm_w) {
    const int t = blockIdx.x;
    const int tid = threadIdx.x;
    __shared__ float red[256];
    __shared__ float yg_s[INTERD];
    float local = 0.f;
    for (int c = tid; c < INTERD; c += 256) {
        const float g = g_proj[(size_t)t * PROJD + c];
        const float yv = g_y[(size_t)t * INTERD + c];
        const float yg = yv * (g / (1.f + __expf(-g)));
        yg_s[c] = yg;
        local += yg * yg;
    }
    red[tid] = local;
    __syncthreads();
    for (int s = 128; s > 0; s >>= 1) {
        if (tid < s) red[tid] += red[tid + s];
        __syncthreads();
    }
    const float rstd = rsqrtf(red[0] / (float)INTERD + 1e-6f);
    __nv_bfloat16* dst = g_Apack + (size_t)t * 3 * INTERD;
    for (int c = tid * 4; c < INTERD; c += 1024) {
        union { __nv_bfloat16 h[4]; uint2 u; } uh, ul;
#pragma unroll
        for (int i = 0; i < 4; i++) {
            const float v = norm_w[c + i] * yg_s[c + i] * rstd;
            uh.h[i] = __float2bfloat16(v);
            ul.h[i] = __float2bfloat16(v - __bfloat162float(uh.h[i]));
        }
        *(uint2*)(dst + c) = uh.u;
        *(uint2*)(dst + INTERD + c) = ul.u;
        *(uint2*)(dst + 2 * INTERD + c) = uh.u;
    }
}

// ---------------- launch ----------------
extern "C" void kernel_launch(void* const* d_in, const int* in_sizes, int n_in,
                              void* d_out, int out_size) {
    (void)in_sizes; (void)n_in; (void)out_size;
    const float* x       = (const float*)d_in[0];
    const float* w_in    = (const float*)d_in[1];
    const float* conv_w  = (const float*)d_in[2];
    const float* conv_b  = (const float*)d_in[3];
    const float* dt_bias = (const float*)d_in[4];
    const float* A_log   = (const float*)d_in[5];
    const float* Dv      = (const float*)d_in[6];
    const float* norm_w  = (const float*)d_in[7];
    const float* w_out   = (const float*)d_in[8];
    float* out = (float*)d_out;

    float* p_proj = nullptr;
    __nv_bfloat16* p_Apack = nullptr;
    __nv_bfloat16* p_B1 = nullptr;
    __nv_bfloat16* p_B2 = nullptr;
    cudaGetSymbolAddress((void**)&p_proj, g_proj);
    cudaGetSymbolAddress((void**)&p_Apack, g_Apack);
    cudaGetSymbolAddress((void**)&p_B1, g_B1);
    cudaGetSymbolAddress((void**)&p_B2, g_B2);

    cudaFuncSetAttribute(tgemm, cudaFuncAttributeMaxDynamicSharedMemorySize, GEMM_DYN_SMEM);
    cudaFuncSetAttribute(ssd_hmma, cudaFuncAttributeMaxDynamicSharedMemorySize, SSD_DYN_SMEM);

    // --- GEMM1 packs (split so tgemm is the 4th launch for ncu) ---
    pack_split<<<2048, 256>>>(x, p_Apack, SS, 0, SS, EMB, 0);
    pack_split<<<2048, 256>>>(w_in, p_B1, PROJD, 0, PROJPAD / 2, EMB, 1);
    pack_split<<<2048, 256>>>(w_in, p_B1, PROJD, PROJPAD / 2, PROJPAD, EMB, 1);
    // --- GEMM1: proj = X @ W_in^T ---
    tgemm<<<dim3(SS / 128, PROJPAD / 128), 256, GEMM_DYN_SMEM>>>(
        p_Apack, p_B1, p_proj, 3 * EMB, PROJD, PROJD);

    // --- elementwise / scan stages ---
    conv_silu_kernel<<<dim3(CONVD / 256, SS / 8), 256>>>(conv_w, conv_b);
    dtacum_kernel<<<dim3(NCH, NH), CSZ>>>(dt_bias, A_log);
    ssd_hmma<<<dim3(NCH, NH), 256, SSD_DYN_SMEM>>>(Dv);
    norm_pack_kernel<<<SS, 256>>>(norm_w);

    // --- GEMM2: out = normed @ W_out^T ---
    pack_split<<<2048, 256>>>(w_out, p_B2, EMB, 0, EMB, INTERD, 1);
    tgemm<<<dim3(SS / 128, EMB / 128), 256, GEMM_DYN_SMEM>>>(
        p_Apack, p_B2, out, 3 * INTERD, EMB, EMB);
}